// round 14
// baseline (speedup 1.0000x reference)
#include <cuda_runtime.h>
#include <cstdint>
#include <math.h>

#define B_   4
#define C_   256
#define H_   8
#define KD   96
#define NN   2048
#define EPSV 1e-6f
#define SCALE 0.10206207261596575f  // 1/sqrt(96)

// Packed scratch layouts (written by proj_tc, consumed by attn_tc):
// g_q2[bh][m][96]  : A-frag packed along k: slot = kb*8 + (j&3)*2 + (j>>2), j=kd&7
// g_k2[bh][kb][n][8]: B-frag packed: slot(j) within kb
// g_z2[bh][kd][npacked]: packed along n within 8-blocks: npos = (n&~7)+(n&3)*2+((n&7)>>2)
static __device__ __align__(256) float g_q2[(size_t)B_*H_*NN*96];
static __device__ __align__(256) float g_k2[(size_t)B_*H_*12*NN*8];
static __device__ __align__(256) float g_z2[(size_t)B_*H_*KD*NN];
static __device__ __align__(256) float g_o [(size_t)B_*C_*3*NN];   // fp32 [b][e][d][m]

__device__ __forceinline__ float to_tf32(float x){
    float r; asm("cvt.rna.tf32.f32 %0, %1;" : "=f"(r) : "f"(x)); return r;
}
__device__ __forceinline__ unsigned fbits(float x){ return __float_as_uint(x); }

__device__ __forceinline__ void mma8(float* d, const unsigned* a, const unsigned* b){
    asm volatile("mma.sync.aligned.m16n8k8.row.col.f32.tf32.tf32.f32 "
        "{%0,%1,%2,%3},{%4,%5,%6,%7},{%8,%9},{%0,%1,%2,%3};\n"
        : "+f"(d[0]),"+f"(d[1]),"+f"(d[2]),"+f"(d[3])
        : "r"(a[0]),"r"(a[1]),"r"(a[2]),"r"(a[3]),"r"(b[0]),"r"(b[1]));
}
__device__ __forceinline__ void cp16(uint32_t dst, const float* src){
    asm volatile("cp.async.cg.shared.global [%0], [%1], 16;\n" :: "r"(dst), "l"(src));
}

// ---------------------------------------------------------------------------
// proj_tc: Y[e][col] = sum_c W[c][e] X[c][col] + bias, tf32 MMA.  (UNCHANGED)
// ---------------------------------------------------------------------------
#define WST 260
#define XST 132
#define POFF_X0 (64*WST)
#define POFF_X1 (POFF_X0 + 32*XST)
#define P_SMEM  (POFF_X1 + 32*XST)   // 25088 floats

__device__ __forceinline__ void store_pkd(int dst, int b, int e, int d, int n, float v){
    int h = e >> 5, c = e & 31, kd = c*3 + d;
    size_t bh = (size_t)(b*H_ + h);
    int j = kd & 7, slot = (j&3)*2 + (j>>2);
    if (dst == 0)      g_q2[(bh*NN + n)*96 + (kd>>3)*8 + slot] = to_tf32(v * SCALE);
    else if (dst == 1) g_k2[((bh*12 + (kd>>3))*NN + n)*8 + slot] = to_tf32(v);
    else               g_z2[(bh*KD + kd)*NN + (n & ~7) + (n&3)*2 + ((n&7)>>2)] = to_tf32(v);
}

__global__ __launch_bounds__(256, 2) void proj_tc(const float* __restrict__ X0,
                                                  const float* __restrict__ W,
                                                  const float* __restrict__ Wb,
                                                  int dst)
{
    extern __shared__ float smp[];
    const int b = blockIdx.z;
    const int colBase = blockIdx.x * 128;
    const int eBase   = blockIdx.y * 64;
    const int tid = threadIdx.x, wid = tid >> 5, lane = tid & 31;
    const int qr = lane >> 2, qc = lane & 3;
    const int wm = wid & 3, wn = wid >> 2;
    const uint32_t sb = (uint32_t)__cvta_generic_to_shared(smp);
    const float* X = X0 + (size_t)b * (C_*3*NN);

    for (int x = tid; x < 1024; x += 256) {
        int c = x >> 5, rem = x & 31;
        cp16(sb + (uint32_t)(POFF_X0 + c*XST + rem*4)*4, X + (size_t)c*(3*NN) + colBase + rem*4);
    }
    asm volatile("cp.async.commit_group;\n");

    for (int x = tid; x < 4096; x += 256) {
        int c = x >> 4, e4 = (x & 15) * 4;
        float4 w = *(const float4*)(W + (size_t)c*C_ + eBase + e4);
        int kb = c >> 3, j = c & 7;
        int slot = kb*8 + (j&3)*2 + (j>>2);
        smp[(e4+0)*WST + slot] = to_tf32(w.x);
        smp[(e4+1)*WST + slot] = to_tf32(w.y);
        smp[(e4+2)*WST + slot] = to_tf32(w.z);
        smp[(e4+3)*WST + slot] = to_tf32(w.w);
    }

    float s[8][4];
#pragma unroll
    for (int nf = 0; nf < 8; nf++){ s[nf][0]=0.f; s[nf][1]=0.f; s[nf][2]=0.f; s[nf][3]=0.f; }

    for (int st = 0; st < 8; st++) {
        asm volatile("cp.async.wait_group 0;\n");
        __syncthreads();
        const int cur = st & 1;
        if (st < 7) {
            const int c0 = (st + 1) * 32;
            const int bo = cur ? POFF_X0 : POFF_X1;
            for (int x = tid; x < 1024; x += 256) {
                int c = x >> 5, rem = x & 31;
                cp16(sb + (uint32_t)(bo + c*XST + rem*4)*4, X + (size_t)(c0 + c)*(3*NN) + colBase + rem*4);
            }
        }
        asm volatile("cp.async.commit_group;\n");
        const float* xb = smp + (cur ? POFF_X1 : POFF_X0);

#pragma unroll
        for (int kbl = 0; kbl < 4; kbl++) {
            const int kb = st*4 + kbl;
            float2 a02 = *(const float2*)(smp + (wm*16+qr)*WST + kb*8 + qc*2);
            float2 a13 = *(const float2*)(smp + (wm*16+qr+8)*WST + kb*8 + qc*2);
            unsigned a[4] = { fbits(a02.x), fbits(a13.x), fbits(a02.y), fbits(a13.y) };
            const float* bp  = xb + (kbl*8+qc)*XST + wn*64 + qr;
            const float* bp4 = bp + 4*XST;
#pragma unroll
            for (int nf = 0; nf < 8; nf++) {
                unsigned bb[2] = { fbits(to_tf32(bp[nf*8])), fbits(to_tf32(bp4[nf*8])) };
                mma8(s[nf], a, bb);
            }
        }
    }

    const int d  = colBase >> 11;
    const int e0 = eBase + wm*16 + qr, e1 = e0 + 8;
    float b00=Wb[e0*3], b01=Wb[e0*3+1], b02=Wb[e0*3+2];
    float b10=Wb[e1*3], b11=Wb[e1*3+1], b12=Wb[e1*3+2];
    const float u0 = EPSV * Wb[e0*3+d] * rsqrtf(b00*b00 + b01*b01 + b02*b02);
    const float u1 = EPSV * Wb[e1*3+d] * rsqrtf(b10*b10 + b11*b11 + b12*b12);
#pragma unroll
    for (int nf = 0; nf < 8; nf++) {
        int col = colBase + wn*64 + nf*8 + 2*qc;
        int n = col & (NN-1);
        store_pkd(dst, b, e0, d, n,   s[nf][0] + u0);
        store_pkd(dst, b, e0, d, n+1, s[nf][1] + u0);
        store_pkd(dst, b, e1, d, n,   s[nf][2] + u1);
        store_pkd(dst, b, e1, d, n+1, s[nf][3] + u1);
    }
}

// ---------------------------------------------------------------------------
// proj_o: fp32 SIMT (exact).  (UNCHANGED)
// ---------------------------------------------------------------------------
#define PBK 16
#define PSP 68

__global__ __launch_bounds__(256) void proj_o(const float* __restrict__ W,
                                              const float* __restrict__ Wb,
                                              float* __restrict__ outp)
{
    __shared__ float Ws[PBK][PSP];
    __shared__ float Xs[PBK][PSP];

    const int b = blockIdx.z;
    const float* X = g_o + (size_t)b * (C_*3*NN);
    const int colBase = blockIdx.x * 64;
    const int eBase   = blockIdx.y * 64;
    const int tid = threadIdx.x;
    const int ty = tid >> 4, tx = tid & 15;
    const int lr = tid >> 4, lc = (tid & 15) * 4;

    float s[4][4];
#pragma unroll
    for (int i = 0; i < 4; i++)
#pragma unroll
        for (int j = 0; j < 4; j++) s[i][j] = 0.f;

    for (int k0 = 0; k0 < C_; k0 += PBK) {
        float4 wv = *(const float4*)(W + (size_t)(k0 + lr) * C_     + eBase   + lc);
        float4 xv = *(const float4*)(X + (size_t)(k0 + lr) * (3*NN) + colBase + lc);
        *(float4*)&Ws[lr][lc] = wv;
        *(float4*)&Xs[lr][lc] = xv;
        __syncthreads();
#pragma unroll
        for (int kk = 0; kk < PBK; kk++) {
            float4 av = *(const float4*)&Ws[kk][ty*4];
            float4 bv = *(const float4*)&Xs[kk][tx*4];
            float ar[4] = {av.x, av.y, av.z, av.w};
            float br[4] = {bv.x, bv.y, bv.z, bv.w};
#pragma unroll
            for (int i = 0; i < 4; i++)
#pragma unroll
                for (int j = 0; j < 4; j++) s[i][j] += ar[i] * br[j];
        }
        __syncthreads();
    }

    const int d  = colBase / NN;
    const int n0 = colBase - d * NN;
#pragma unroll
    for (int i = 0; i < 4; i++) {
        const int e = eBase + ty*4 + i;
        const float b0 = Wb[e*3+0], b1 = Wb[e*3+1], b2 = Wb[e*3+2];
        const float u  = EPSV * Wb[e*3 + d] * rsqrtf(b0*b0 + b1*b1 + b2*b2);
        const size_t rowIdx = ((size_t)((b*C_ + e)*3 + d)) * NN;
#pragma unroll
        for (int j = 0; j < 4; j++)
            outp[rowIdx + n0 + tx*4 + j] = s[i][j] + u;
    }
}

// ---------------------------------------------------------------------------
// attn_tc v3: 512 threads / 16 warps (4 per SMSP) for latency hiding.
// Warp (wm = wid&7, wn = wid>>3): GEMM1 computes S[16 x 32] (n-half wn),
// softmax reduced cross-warp via smem partials, GEMM2 computes the wn-half
// of kd (48 rows) for m-cols wm*16..+16.
// ---------------------------------------------------------------------------
#define QST 100
#define ZST 68
#define PST 68
#define OFF_Q  0
#define OFF_K0 12800
#define OFF_K1 18944
#define OFF_Z0 25088
#define OFF_Z1 31616
#define OFF_P  38144
#define OFF_F  46848
#define OFF_PM 46976
#define OFF_PS 47232
#define SMEM_F 47488   // floats -> 189952 B

__global__ __launch_bounds__(512) void attn_tc()
{
    extern __shared__ float sm[];
    const int bh = blockIdx.z * H_ + blockIdx.y;
    const int b = blockIdx.z, h = blockIdx.y;
    const int m0 = blockIdx.x * 128;
    const int tid = threadIdx.x, wid = tid >> 5, lane = tid & 31;
    const int qr = lane >> 2, qc = lane & 3;
    const int wm = wid & 7, wn = wid >> 3;
    const uint32_t sb = (uint32_t)__cvta_generic_to_shared(sm);

    const float* qg = g_q2 + ((size_t)bh*NN + m0)*96;
    const float* kg = g_k2 + (size_t)bh*12*NN*8;
    const float* zg = g_z2 + (size_t)bh*KD*NN;

    // Q tile: 128 rows x 96 packed floats
    for (int x = tid; x < 3072; x += 512) {
        int m = x / 24, rem = x - m*24;
        cp16(sb + (uint32_t)(OFF_Q + m*QST + rem*4)*4, qg + (size_t)m*96 + rem*4);
    }
    // K/Z tile 0
    for (int x = tid; x < 1536; x += 512) {
        int kb = x >> 7, rem = x & 127;
        cp16(sb + (uint32_t)(OFF_K0 + kb*512 + rem*4)*4, kg + (size_t)kb*NN*8 + rem*4);
    }
    for (int x = tid; x < 1536; x += 512) {
        int kd = x >> 4, rem = x & 15;
        cp16(sb + (uint32_t)(OFF_Z0 + kd*ZST + rem*4)*4, zg + (size_t)kd*NN + rem*4);
    }
    asm volatile("cp.async.commit_group;\n");

    float sO[3][2][4];
#pragma unroll
    for (int mf = 0; mf < 3; mf++)
#pragma unroll
        for (int g = 0; g < 2; g++)
#pragma unroll
            for (int c = 0; c < 4; c++) sO[mf][g][c] = 0.f;

    float mi0 = -1e30f, mi1 = -1e30f, li0 = 0.f, li1 = 0.f;
    const int sa = ((2*qc)&3)*2 + ((2*qc)>>2);
    const int sbslot = ((2*qc+1)&3)*2 + ((2*qc+1)>>2);
    const int r0 = wm*16 + qr;

    for (int t = 0; t < 32; t++) {
        asm volatile("cp.async.wait_group 0;\n");
        __syncthreads();                       // sync #1
        const int cur = t & 1;
        if (t < 31) {
            const int n0 = (t + 1) * 64;
            const int bk = cur ? OFF_K0 : OFF_K1;
            const int bz = cur ? OFF_Z0 : OFF_Z1;
            for (int x = tid; x < 1536; x += 512) {
                int kb = x >> 7, rem = x & 127;
                cp16(sb + (uint32_t)(bk + kb*512 + rem*4)*4, kg + ((size_t)kb*NN + n0)*8 + rem*4);
            }
            for (int x = tid; x < 1536; x += 512) {
                int kd = x >> 4, rem = x & 15;
                cp16(sb + (uint32_t)(bz + kd*ZST + rem*4)*4, zg + (size_t)kd*NN + n0 + rem*4);
            }
        }
        asm volatile("cp.async.commit_group;\n");

        const float* kbuf = sm + (cur ? OFF_K1 : OFF_K0);
        const float* zbuf = sm + (cur ? OFF_Z1 : OFF_Z0);

        // ---- GEMM1: S (16 x 32 per warp, n-half wn) ----
        float s[4][4];
#pragma unroll
        for (int nf = 0; nf < 4; nf++){ s[nf][0]=0.f; s[nf][1]=0.f; s[nf][2]=0.f; s[nf][3]=0.f; }

        const float* ar0 = sm + OFF_Q + (wm*16 + qr)*QST + qc*2;
        const float* ar1 = ar0 + 8*QST;
#pragma unroll
        for (int kb = 0; kb < 12; kb++) {
            float2 a02 = *(const float2*)(ar0 + kb*8);
            float2 a13 = *(const float2*)(ar1 + kb*8);
            unsigned a[4] = { fbits(a02.x), fbits(a13.x), fbits(a02.y), fbits(a13.y) };
            const float* bp = kbuf + kb*512 + wn*256 + qr*8 + qc*2;
#pragma unroll
            for (int nf = 0; nf < 4; nf++) {
                float2 b2 = *(const float2*)(bp + nf*64);
                unsigned bb[2] = { fbits(b2.x), fbits(b2.y) };
                mma8(s[nf], a, bb);
            }
        }

        // ---- cross-warp online softmax ----
        float rm0 = -1e30f, rm1 = -1e30f;
#pragma unroll
        for (int nf = 0; nf < 4; nf++) {
            rm0 = fmaxf(rm0, fmaxf(s[nf][0], s[nf][1]));
            rm1 = fmaxf(rm1, fmaxf(s[nf][2], s[nf][3]));
        }
        rm0 = fmaxf(rm0, __shfl_xor_sync(0xffffffffu, rm0, 1));
        rm0 = fmaxf(rm0, __shfl_xor_sync(0xffffffffu, rm0, 2));
        rm1 = fmaxf(rm1, __shfl_xor_sync(0xffffffffu, rm1, 1));
        rm1 = fmaxf(rm1, __shfl_xor_sync(0xffffffffu, rm1, 2));
        if (qc == 0) {
            sm[OFF_PM + wn*128 + r0]     = rm0;
            sm[OFF_PM + wn*128 + r0 + 8] = rm1;
        }
        __syncthreads();                       // sync #2
        float gm0 = fmaxf(sm[OFF_PM + r0],     sm[OFF_PM + 128 + r0]);
        float gm1 = fmaxf(sm[OFF_PM + r0 + 8], sm[OFF_PM + 128 + r0 + 8]);
        float nm0 = fmaxf(mi0, gm0), nm1 = fmaxf(mi1, gm1);
        float f0 = __expf(mi0 - nm0), f1 = __expf(mi1 - nm1);
        mi0 = nm0; mi1 = nm1;
        float sum0 = 0.f, sum1 = 0.f;
#pragma unroll
        for (int nf = 0; nf < 4; nf++) {
            s[nf][0] = __expf(s[nf][0] - nm0); s[nf][1] = __expf(s[nf][1] - nm0);
            s[nf][2] = __expf(s[nf][2] - nm1); s[nf][3] = __expf(s[nf][3] - nm1);
            sum0 += s[nf][0] + s[nf][1];
            sum1 += s[nf][2] + s[nf][3];
        }
        sum0 += __shfl_xor_sync(0xffffffffu, sum0, 1);
        sum0 += __shfl_xor_sync(0xffffffffu, sum0, 2);
        sum1 += __shfl_xor_sync(0xffffffffu, sum1, 1);
        sum1 += __shfl_xor_sync(0xffffffffu, sum1, 2);
        if (qc == 0) {
            sm[OFF_PS + wn*128 + r0]     = sum0;
            sm[OFF_PS + wn*128 + r0 + 8] = sum1;
            if (wn == 0) {
                sm[OFF_F + r0]     = f0;
                sm[OFF_F + r0 + 8] = f1;
            }
        }
        // P -> smem [m][packed n], tf32, n-half wn
        {
            float* pr0 = sm + OFF_P + (wm*16 + qr)*PST + wn*32;
            float* pr1 = pr0 + 8*PST;
#pragma unroll
            for (int nf = 0; nf < 4; nf++) {
                pr0[nf*8 + sa]     = to_tf32(s[nf][0]);
                pr0[nf*8 + sbslot] = to_tf32(s[nf][1]);
                pr1[nf*8 + sa]     = to_tf32(s[nf][2]);
                pr1[nf*8 + sbslot] = to_tf32(s[nf][3]);
            }
        }
        __syncthreads();                       // sync #3
        li0 = li0 * f0 + sm[OFF_PS + r0]     + sm[OFF_PS + 128 + r0];
        li1 = li1 * f1 + sm[OFF_PS + r0 + 8] + sm[OFF_PS + 128 + r0 + 8];

        const float fc00 = sm[OFF_F + wm*16 + 2*qc];
        const float fc01 = sm[OFF_F + wm*16 + 2*qc + 1];
        const float fc10 = sm[OFF_F + wm*16 + 8 + 2*qc];
        const float fc11 = sm[OFF_F + wm*16 + 8 + 2*qc + 1];
#pragma unroll
        for (int mf = 0; mf < 3; mf++) {
            sO[mf][0][0] *= fc00; sO[mf][0][1] *= fc01; sO[mf][0][2] *= fc00; sO[mf][0][3] *= fc01;
            sO[mf][1][0] *= fc10; sO[mf][1][1] *= fc11; sO[mf][1][2] *= fc10; sO[mf][1][3] *= fc11;
        }

        // ---- GEMM2: O'[kd-half wn][m-cols wm*16..] += Z * P^T ----
        const float* prd0 = sm + OFF_P + (wm*16 + qr)*PST + qc*2;
        const float* prd1 = prd0 + 8*PST;
#pragma unroll
        for (int nb = 0; nb < 8; nb++) {
            float2 p0 = *(const float2*)(prd0 + nb*8);
            float2 p1 = *(const float2*)(prd1 + nb*8);
            unsigned bp0[2] = { fbits(p0.x), fbits(p0.y) };
            unsigned bp1[2] = { fbits(p1.x), fbits(p1.y) };
            const float* zr = zbuf + nb*8 + qc*2;
#pragma unroll
            for (int mf = 0; mf < 3; mf++) {
                float2 z02 = *(const float2*)(zr + (wn*48 + mf*16 + qr)*ZST);
                float2 z13 = *(const float2*)(zr + (wn*48 + mf*16 + qr + 8)*ZST);
                unsigned a[4] = { fbits(z02.x), fbits(z13.x), fbits(z02.y), fbits(z13.y) };
                mma8(sO[mf][0], a, bp0);
                mma8(sO[mf][1], a, bp1);
            }
        }
    }

    // publish li, then barrier (also the race fix: os overlaps K1/Z0-head)
    if (qc == 0 && wn == 0) {
        sm[OFF_F + r0]     = li0;
        sm[OFF_F + r0 + 8] = li1;
    }
    __syncthreads();

    const float ic00 = 1.f / sm[OFF_F + wm*16 + 2*qc];
    const float ic01 = 1.f / sm[OFF_F + wm*16 + 2*qc + 1];
    const float ic10 = 1.f / sm[OFF_F + wm*16 + 8 + 2*qc];
    const float ic11 = 1.f / sm[OFF_F + wm*16 + 8 + 2*qc + 1];

    float* os = sm + OFF_K0;   // 96 x 132 staging
#pragma unroll
    for (int mf = 0; mf < 3; mf++) {
        const int rr = wn*48 + mf*16 + qr;
        const int mc = wm*16 + 2*qc;
        os[rr*132 + mc]         = sO[mf][0][0] * ic00;
        os[rr*132 + mc + 1]     = sO[mf][0][1] * ic01;
        os[(rr+8)*132 + mc]     = sO[mf][0][2] * ic00;
        os[(rr+8)*132 + mc + 1] = sO[mf][0][3] * ic01;
        os[rr*132 + mc + 8]     = sO[mf][1][0] * ic10;
        os[rr*132 + mc + 9]     = sO[mf][1][1] * ic11;
        os[(rr+8)*132 + mc + 8] = sO[mf][1][2] * ic10;
        os[(rr+8)*132 + mc + 9] = sO[mf][1][3] * ic11;
    }
    __syncthreads();
    for (int x = tid; x < KD*32; x += 512) {
        int kd = x >> 5, mq = (x & 31) << 2;
        float4 v = *(const float4*)&os[kd*132 + mq];
        int c = kd / 3, d = kd - 3*c;
        *(float4*)(g_o + ((size_t)((b*C_ + h*32 + c)*3 + d))*NN + m0 + mq) = v;
    }
}

// ---------------------------------------------------------------------------
extern "C" void kernel_launch(void* const* d_in, const int* in_sizes, int n_in,
                              void* d_out, int out_size)
{
    const float* Q    = (const float*)d_in[0];
    const float* K    = (const float*)d_in[1];
    const float* Z    = (const float*)d_in[2];
    const float* Wq_w = (const float*)d_in[3];
    const float* Wq_b = (const float*)d_in[4];
    const float* Wk_w = (const float*)d_in[5];
    const float* Wk_b = (const float*)d_in[6];
    const float* Wz_w = (const float*)d_in[7];
    const float* Wz_b = (const float*)d_in[8];
    const float* Wo_w = (const float*)d_in[9];
    const float* Wo_b = (const float*)d_in[10];
    float* out = (float*)d_out;

    static int init = 0;
    if (!init) {
        cudaFuncSetAttribute(proj_tc, cudaFuncAttributeMaxDynamicSharedMemorySize, P_SMEM*4);
        cudaFuncSetAttribute(attn_tc, cudaFuncAttributeMaxDynamicSharedMemorySize, SMEM_F*4);
        init = 1;
    }

    dim3 tgrid(48, 4, B_);
    proj_tc<<<tgrid, 256, P_SMEM*4>>>(Q, Wq_w, Wq_b, 0);
    proj_tc<<<tgrid, 256, P_SMEM*4>>>(K, Wk_w, Wk_b, 1);
    proj_tc<<<tgrid, 256, P_SMEM*4>>>(Z, Wz_w, Wz_b, 2);

    dim3 agrid(NN/128, H_, B_);   // (16, 8, 4)
    attn_tc<<<agrid, 512, SMEM_F*4>>>();

    dim3 ogrid((3*NN)/64, C_/64, B_);
    proj_o<<<ogrid, 256>>>(Wo_w, Wo_b, out);
}

// round 16
// speedup vs baseline: 1.6342x; 1.6342x over previous
#include <cuda_runtime.h>
#include <cstdint>
#include <math.h>

#define B_   4
#define C_   256
#define H_   8
#define KD   96
#define NN   2048
#define EPSV 1e-6f
#define SCALE 0.10206207261596575f  // 1/sqrt(96)

static __device__ __align__(256) float g_q2[(size_t)B_*H_*NN*96];
static __device__ __align__(256) float g_k2[(size_t)B_*H_*12*NN*8];
static __device__ __align__(256) float g_z2[(size_t)B_*H_*KD*NN];
static __device__ __align__(256) float g_o [(size_t)B_*C_*3*NN];   // fp32 [b][e][d][m]

__device__ __forceinline__ float to_tf32(float x){
    float r; asm("cvt.rna.tf32.f32 %0, %1;" : "=f"(r) : "f"(x)); return r;
}
__device__ __forceinline__ unsigned fbits(float x){ return __float_as_uint(x); }

__device__ __forceinline__ void mma8(float* d, const unsigned* a, const unsigned* b){
    asm volatile("mma.sync.aligned.m16n8k8.row.col.f32.tf32.tf32.f32 "
        "{%0,%1,%2,%3},{%4,%5,%6,%7},{%8,%9},{%0,%1,%2,%3};\n"
        : "+f"(d[0]),"+f"(d[1]),"+f"(d[2]),"+f"(d[3])
        : "r"(a[0]),"r"(a[1]),"r"(a[2]),"r"(a[3]),"r"(b[0]),"r"(b[1]));
}
__device__ __forceinline__ void cp16(uint32_t dst, const float* src){
    asm volatile("cp.async.cg.shared.global [%0], [%1], 16;\n" :: "r"(dst), "l"(src));
}

// ---------------------------------------------------------------------------
// proj_tc  (UNCHANGED from the 846us config)
// ---------------------------------------------------------------------------
#define WST 260
#define XST 132
#define POFF_X0 (64*WST)
#define POFF_X1 (POFF_X0 + 32*XST)
#define P_SMEM  (POFF_X1 + 32*XST)

__device__ __forceinline__ void store_pkd(int dst, int b, int e, int d, int n, float v){
    int h = e >> 5, c = e & 31, kd = c*3 + d;
    size_t bh = (size_t)(b*H_ + h);
    int j = kd & 7, slot = (j&3)*2 + (j>>2);
    if (dst == 0)      g_q2[(bh*NN + n)*96 + (kd>>3)*8 + slot] = to_tf32(v * SCALE);
    else if (dst == 1) g_k2[((bh*12 + (kd>>3))*NN + n)*8 + slot] = to_tf32(v);
    else               g_z2[(bh*KD + kd)*NN + (n & ~7) + (n&3)*2 + ((n&7)>>2)] = to_tf32(v);
}

__global__ __launch_bounds__(256, 2) void proj_tc(const float* __restrict__ X0,
                                                  const float* __restrict__ W,
                                                  const float* __restrict__ Wb,
                                                  int dst)
{
    extern __shared__ float smp[];
    const int b = blockIdx.z;
    const int colBase = blockIdx.x * 128;
    const int eBase   = blockIdx.y * 64;
    const int tid = threadIdx.x, wid = tid >> 5, lane = tid & 31;
    const int qr = lane >> 2, qc = lane & 3;
    const int wm = wid & 3, wn = wid >> 2;
    const uint32_t sb = (uint32_t)__cvta_generic_to_shared(smp);
    const float* X = X0 + (size_t)b * (C_*3*NN);

    for (int x = tid; x < 1024; x += 256) {
        int c = x >> 5, rem = x & 31;
        cp16(sb + (uint32_t)(POFF_X0 + c*XST + rem*4)*4, X + (size_t)c*(3*NN) + colBase + rem*4);
    }
    asm volatile("cp.async.commit_group;\n");

    for (int x = tid; x < 4096; x += 256) {
        int c = x >> 4, e4 = (x & 15) * 4;
        float4 w = *(const float4*)(W + (size_t)c*C_ + eBase + e4);
        int kb = c >> 3, j = c & 7;
        int slot = kb*8 + (j&3)*2 + (j>>2);
        smp[(e4+0)*WST + slot] = to_tf32(w.x);
        smp[(e4+1)*WST + slot] = to_tf32(w.y);
        smp[(e4+2)*WST + slot] = to_tf32(w.z);
        smp[(e4+3)*WST + slot] = to_tf32(w.w);
    }

    float s[8][4];
#pragma unroll
    for (int nf = 0; nf < 8; nf++){ s[nf][0]=0.f; s[nf][1]=0.f; s[nf][2]=0.f; s[nf][3]=0.f; }

    for (int st = 0; st < 8; st++) {
        asm volatile("cp.async.wait_group 0;\n");
        __syncthreads();
        const int cur = st & 1;
        if (st < 7) {
            const int c0 = (st + 1) * 32;
            const int bo = cur ? POFF_X0 : POFF_X1;
            for (int x = tid; x < 1024; x += 256) {
                int c = x >> 5, rem = x & 31;
                cp16(sb + (uint32_t)(bo + c*XST + rem*4)*4, X + (size_t)(c0 + c)*(3*NN) + colBase + rem*4);
            }
        }
        asm volatile("cp.async.commit_group;\n");
        const float* xb = smp + (cur ? POFF_X1 : POFF_X0);

#pragma unroll
        for (int kbl = 0; kbl < 4; kbl++) {
            const int kb = st*4 + kbl;
            float2 a02 = *(const float2*)(smp + (wm*16+qr)*WST + kb*8 + qc*2);
            float2 a13 = *(const float2*)(smp + (wm*16+qr+8)*WST + kb*8 + qc*2);
            unsigned a[4] = { fbits(a02.x), fbits(a13.x), fbits(a02.y), fbits(a13.y) };
            const float* bp  = xb + (kbl*8+qc)*XST + wn*64 + qr;
            const float* bp4 = bp + 4*XST;
#pragma unroll
            for (int nf = 0; nf < 8; nf++) {
                unsigned bb[2] = { fbits(to_tf32(bp[nf*8])), fbits(to_tf32(bp4[nf*8])) };
                mma8(s[nf], a, bb);
            }
        }
    }

    const int d  = colBase >> 11;
    const int e0 = eBase + wm*16 + qr, e1 = e0 + 8;
    float b00=Wb[e0*3], b01=Wb[e0*3+1], b02=Wb[e0*3+2];
    float b10=Wb[e1*3], b11=Wb[e1*3+1], b12=Wb[e1*3+2];
    const float u0 = EPSV * Wb[e0*3+d] * rsqrtf(b00*b00 + b01*b01 + b02*b02);
    const float u1 = EPSV * Wb[e1*3+d] * rsqrtf(b10*b10 + b11*b11 + b12*b12);
#pragma unroll
    for (int nf = 0; nf < 8; nf++) {
        int col = colBase + wn*64 + nf*8 + 2*qc;
        int n = col & (NN-1);
        store_pkd(dst, b, e0, d, n,   s[nf][0] + u0);
        store_pkd(dst, b, e0, d, n+1, s[nf][1] + u0);
        store_pkd(dst, b, e1, d, n,   s[nf][2] + u1);
        store_pkd(dst, b, e1, d, n+1, s[nf][3] + u1);
    }
}

// ---------------------------------------------------------------------------
// proj_o  (UNCHANGED)
// ---------------------------------------------------------------------------
#define PBK 16
#define PSP 68

__global__ __launch_bounds__(256) void proj_o(const float* __restrict__ W,
                                              const float* __restrict__ Wb,
                                              float* __restrict__ outp)
{
    __shared__ float Ws[PBK][PSP];
    __shared__ float Xs[PBK][PSP];

    const int b = blockIdx.z;
    const float* X = g_o + (size_t)b * (C_*3*NN);
    const int colBase = blockIdx.x * 64;
    const int eBase   = blockIdx.y * 64;
    const int tid = threadIdx.x;
    const int ty = tid >> 4, tx = tid & 15;
    const int lr = tid >> 4, lc = (tid & 15) * 4;

    float s[4][4];
#pragma unroll
    for (int i = 0; i < 4; i++)
#pragma unroll
        for (int j = 0; j < 4; j++) s[i][j] = 0.f;

    for (int k0 = 0; k0 < C_; k0 += PBK) {
        float4 wv = *(const float4*)(W + (size_t)(k0 + lr) * C_     + eBase   + lc);
        float4 xv = *(const float4*)(X + (size_t)(k0 + lr) * (3*NN) + colBase + lc);
        *(float4*)&Ws[lr][lc] = wv;
        *(float4*)&Xs[lr][lc] = xv;
        __syncthreads();
#pragma unroll
        for (int kk = 0; kk < PBK; kk++) {
            float4 av = *(const float4*)&Ws[kk][ty*4];
            float4 bv = *(const float4*)&Xs[kk][tx*4];
            float ar[4] = {av.x, av.y, av.z, av.w};
            float br[4] = {bv.x, bv.y, bv.z, bv.w};
#pragma unroll
            for (int i = 0; i < 4; i++)
#pragma unroll
                for (int j = 0; j < 4; j++) s[i][j] += ar[i] * br[j];
        }
        __syncthreads();
    }

    const int d  = colBase / NN;
    const int n0 = colBase - d * NN;
#pragma unroll
    for (int i = 0; i < 4; i++) {
        const int e = eBase + ty*4 + i;
        const float b0 = Wb[e*3+0], b1 = Wb[e*3+1], b2 = Wb[e*3+2];
        const float u  = EPSV * Wb[e*3 + d] * rsqrtf(b0*b0 + b1*b1 + b2*b2);
        const size_t rowIdx = ((size_t)((b*C_ + e)*3 + d)) * NN;
#pragma unroll
        for (int j = 0; j < 4; j++)
            outp[rowIdx + n0 + tx*4 + j] = s[i][j] + u;
    }
}

// ---------------------------------------------------------------------------
// attn_tc v4: 512 thr / 16 warps, ONE barrier per tile (v2 structure).
// Warp (wm, wn): wn owns a 32-col n-slice of every tile with an INDEPENDENT
// online-softmax stream (own mi/li/O-partial). Streams merged exactly once
// at the end. No per-tile cross-warp communication; f broadcast via shfl.
// ---------------------------------------------------------------------------
#define QST 100
#define ZST 68
#define PST 68
#define OFF_Q  0
#define OFF_K0 12800
#define OFF_K1 18944
#define OFF_Z0 25088
#define OFF_Z1 31616
#define OFF_P  38144
#define OFF_PM 46848
#define OFF_PS 47104
#define SMEM_F 47360   // floats -> 189440 B

__global__ __launch_bounds__(512) void attn_tc()
{
    extern __shared__ float sm[];
    const int bh = blockIdx.z * H_ + blockIdx.y;
    const int b = blockIdx.z, h = blockIdx.y;
    const int m0 = blockIdx.x * 128;
    const int tid = threadIdx.x, wid = tid >> 5, lane = tid & 31;
    const int qr = lane >> 2, qc = lane & 3;
    const int wm = wid & 7, wn = wid >> 3;
    const uint32_t sb = (uint32_t)__cvta_generic_to_shared(sm);

    const float* qg = g_q2 + ((size_t)bh*NN + m0)*96;
    const float* kg = g_k2 + (size_t)bh*12*NN*8;
    const float* zg = g_z2 + (size_t)bh*KD*NN;

    for (int x = tid; x < 3072; x += 512) {
        int m = x / 24, rem = x - m*24;
        cp16(sb + (uint32_t)(OFF_Q + m*QST + rem*4)*4, qg + (size_t)m*96 + rem*4);
    }
    for (int x = tid; x < 1536; x += 512) {
        int kb = x >> 7, rem = x & 127;
        cp16(sb + (uint32_t)(OFF_K0 + kb*512 + rem*4)*4, kg + (size_t)kb*NN*8 + rem*4);
    }
    for (int x = tid; x < 1536; x += 512) {
        int kd = x >> 4, rem = x & 15;
        cp16(sb + (uint32_t)(OFF_Z0 + kd*ZST + rem*4)*4, zg + (size_t)kd*NN + rem*4);
    }
    asm volatile("cp.async.commit_group;\n");

    float sO[6][2][4];
#pragma unroll
    for (int mf = 0; mf < 6; mf++)
#pragma unroll
        for (int g = 0; g < 2; g++)
#pragma unroll
            for (int c = 0; c < 4; c++) sO[mf][g][c] = 0.f;

    float mi0 = -1e30f, mi1 = -1e30f, li0 = 0.f, li1 = 0.f;
    const int sa = ((2*qc)&3)*2 + ((2*qc)>>2);
    const int sbslot = ((2*qc+1)&3)*2 + ((2*qc+1)>>2);

    for (int t = 0; t < 32; t++) {
        asm volatile("cp.async.wait_group 0;\n");
        __syncthreads();                       // the ONE barrier per tile
        const int cur = t & 1;
        if (t < 31) {
            const int n0 = (t + 1) * 64;
            const int bk = cur ? OFF_K0 : OFF_K1;
            const int bz = cur ? OFF_Z0 : OFF_Z1;
            for (int x = tid; x < 1536; x += 512) {
                int kb = x >> 7, rem = x & 127;
                cp16(sb + (uint32_t)(bk + kb*512 + rem*4)*4, kg + ((size_t)kb*NN + n0)*8 + rem*4);
            }
            for (int x = tid; x < 1536; x += 512) {
                int kd = x >> 4, rem = x & 15;
                cp16(sb + (uint32_t)(bz + kd*ZST + rem*4)*4, zg + (size_t)kd*NN + n0 + rem*4);
            }
        }
        asm volatile("cp.async.commit_group;\n");

        const float* kbuf = sm + (cur ? OFF_K1 : OFF_K0);
        const float* zbuf = sm + (cur ? OFF_Z1 : OFF_Z0);

        // ---- GEMM1: S (16 x 32, this warp's n-slice) ----
        float s[4][4];
#pragma unroll
        for (int nf = 0; nf < 4; nf++){ s[nf][0]=0.f; s[nf][1]=0.f; s[nf][2]=0.f; s[nf][3]=0.f; }

        const float* ar0 = sm + OFF_Q + (wm*16 + qr)*QST + qc*2;
        const float* ar1 = ar0 + 8*QST;
#pragma unroll
        for (int kb = 0; kb < 12; kb++) {
            float2 a02 = *(const float2*)(ar0 + kb*8);
            float2 a13 = *(const float2*)(ar1 + kb*8);
            unsigned a[4] = { fbits(a02.x), fbits(a13.x), fbits(a02.y), fbits(a13.y) };
            const float* bp = kbuf + kb*512 + wn*256 + qr*8 + qc*2;
#pragma unroll
            for (int nf = 0; nf < 4; nf++) {
                float2 b2 = *(const float2*)(bp + nf*64);
                unsigned bb[2] = { fbits(b2.x), fbits(b2.y) };
                mma8(s[nf], a, bb);
            }
        }

        // ---- warp-local online softmax (this warp's stream) ----
        float rm0 = -1e30f, rm1 = -1e30f;
#pragma unroll
        for (int nf = 0; nf < 4; nf++) {
            rm0 = fmaxf(rm0, fmaxf(s[nf][0], s[nf][1]));
            rm1 = fmaxf(rm1, fmaxf(s[nf][2], s[nf][3]));
        }
        rm0 = fmaxf(rm0, __shfl_xor_sync(0xffffffffu, rm0, 1));
        rm0 = fmaxf(rm0, __shfl_xor_sync(0xffffffffu, rm0, 2));
        rm1 = fmaxf(rm1, __shfl_xor_sync(0xffffffffu, rm1, 1));
        rm1 = fmaxf(rm1, __shfl_xor_sync(0xffffffffu, rm1, 2));
        float nm0 = fmaxf(mi0, rm0), nm1 = fmaxf(mi1, rm1);
        float f0 = __expf(mi0 - nm0), f1 = __expf(mi1 - nm1);
        mi0 = nm0; mi1 = nm1;
        float sum0 = 0.f, sum1 = 0.f;
#pragma unroll
        for (int nf = 0; nf < 4; nf++) {
            s[nf][0] = __expf(s[nf][0] - nm0); s[nf][1] = __expf(s[nf][1] - nm0);
            s[nf][2] = __expf(s[nf][2] - nm1); s[nf][3] = __expf(s[nf][3] - nm1);
            sum0 += s[nf][0] + s[nf][1];
            sum1 += s[nf][2] + s[nf][3];
        }
        sum0 += __shfl_xor_sync(0xffffffffu, sum0, 1);
        sum0 += __shfl_xor_sync(0xffffffffu, sum0, 2);
        sum1 += __shfl_xor_sync(0xffffffffu, sum1, 1);
        sum1 += __shfl_xor_sync(0xffffffffu, sum1, 2);
        li0 = li0 * f0 + sum0;
        li1 = li1 * f1 + sum1;

        // f broadcast to accumulator columns via shfl (rows 2qc, 2qc+1, +8)
        const float fc00 = __shfl_sync(0xffffffffu, f0, (2*qc)*4);
        const float fc01 = __shfl_sync(0xffffffffu, f0, (2*qc+1)*4);
        const float fc10 = __shfl_sync(0xffffffffu, f1, (2*qc)*4);
        const float fc11 = __shfl_sync(0xffffffffu, f1, (2*qc+1)*4);

        // P -> smem (warp-private 32-col half)
        {
            float* pr0 = sm + OFF_P + (wm*16 + qr)*PST + wn*32;
            float* pr1 = pr0 + 8*PST;
#pragma unroll
            for (int nf = 0; nf < 4; nf++) {
                pr0[nf*8 + sa]     = to_tf32(s[nf][0]);
                pr0[nf*8 + sbslot] = to_tf32(s[nf][1]);
                pr1[nf*8 + sa]     = to_tf32(s[nf][2]);
                pr1[nf*8 + sbslot] = to_tf32(s[nf][3]);
            }
        }
        __syncwarp();

#pragma unroll
        for (int mf = 0; mf < 6; mf++) {
            sO[mf][0][0] *= fc00; sO[mf][0][1] *= fc01; sO[mf][0][2] *= fc00; sO[mf][0][3] *= fc01;
            sO[mf][1][0] *= fc10; sO[mf][1][1] *= fc11; sO[mf][1][2] *= fc10; sO[mf][1][3] *= fc11;
        }

        // ---- GEMM2: O_partial[kd][m-cols] += Z(half) * P^T(half) ----
        const float* prd0 = sm + OFF_P + (wm*16 + qr)*PST + wn*32 + qc*2;
        const float* prd1 = prd0 + 8*PST;
#pragma unroll
        for (int nb = 0; nb < 4; nb++) {
            float2 p0 = *(const float2*)(prd0 + nb*8);
            float2 p1 = *(const float2*)(prd1 + nb*8);
            unsigned bp0[2] = { fbits(p0.x), fbits(p0.y) };
            unsigned bp1[2] = { fbits(p1.x), fbits(p1.y) };
            const float* zr = zbuf + wn*32 + nb*8 + qc*2;
#pragma unroll
            for (int mf = 0; mf < 6; mf++) {
                float2 z02 = *(const float2*)(zr + (mf*16 + qr)*ZST);
                float2 z13 = *(const float2*)(zr + (mf*16 + qr + 8)*ZST);
                unsigned a[4] = { fbits(z02.x), fbits(z13.x), fbits(z02.y), fbits(z13.y) };
                mma8(sO[mf][0], a, bp0);
                mma8(sO[mf][1], a, bp1);
            }
        }
    }

    // ---- end: merge the two softmax streams (exact) ----
    if (qc == 0) {
        sm[OFF_PM + wn*128 + wm*16 + qr]     = mi0;
        sm[OFF_PM + wn*128 + wm*16 + qr + 8] = mi1;
        sm[OFF_PS + wn*128 + wm*16 + qr]     = li0;
        sm[OFF_PS + wn*128 + wm*16 + qr + 8] = li1;
    }
    __syncthreads();   // also fences os-vs-K1/Z reads (race fix)

    // per-accum-column merge factors g = exp(m_wn - mt) / lt
    float gcol[4];
    {
        const int cols[4] = { wm*16 + 2*qc, wm*16 + 2*qc + 1,
                              wm*16 + 8 + 2*qc, wm*16 + 8 + 2*qc + 1 };
#pragma unroll
        for (int i = 0; i < 4; i++) {
            float mA = sm[OFF_PM + cols[i]], mB = sm[OFF_PM + 128 + cols[i]];
            float lA = sm[OFF_PS + cols[i]], lB = sm[OFF_PS + 128 + cols[i]];
            float mt = fmaxf(mA, mB);
            float eA = __expf(mA - mt), eB = __expf(mB - mt);
            float lt = lA*eA + lB*eB;
            gcol[i] = (wn == 0 ? eA : eB) / lt;
        }
    }

    float* os = sm + OFF_K0;   // 96 x 132 staging
    if (wn == 0) {
#pragma unroll
        for (int mf = 0; mf < 6; mf++) {
            const int rr = mf*16 + qr;
            const int mc = wm*16 + 2*qc;
            os[rr*132 + mc]         = sO[mf][0][0] * gcol[0];
            os[rr*132 + mc + 1]     = sO[mf][0][1] * gcol[1];
            os[(rr+8)*132 + mc]     = sO[mf][0][2] * gcol[0];
            os[(rr+8)*132 + mc + 1] = sO[mf][0][3] * gcol[1];
            os[rr*132 + mc + 8]     = sO[mf][1][0] * gcol[2];
            os[rr*132 + mc + 9]     = sO[mf][1][1] * gcol[3];
            os[(rr+8)*132 + mc + 8] = sO[mf][1][2] * gcol[2];
            os[(rr+8)*132 + mc + 9] = sO[mf][1][3] * gcol[3];
        }
    }
    __syncthreads();
    if (wn == 1) {
#pragma unroll
        for (int mf = 0; mf < 6; mf++) {
            const int rr = mf*16 + qr;
            const int mc = wm*16 + 2*qc;
            os[rr*132 + mc]         += sO[mf][0][0] * gcol[0];
            os[rr*132 + mc + 1]     += sO[mf][0][1] * gcol[1];
            os[(rr+8)*132 + mc]     += sO[mf][0][2] * gcol[0];
            os[(rr+8)*132 + mc + 1] += sO[mf][0][3] * gcol[1];
            os[rr*132 + mc + 8]     += sO[mf][1][0] * gcol[2];
            os[rr*132 + mc + 9]     += sO[mf][1][1] * gcol[3];
            os[(rr+8)*132 + mc + 8] += sO[mf][1][2] * gcol[2];
            os[(rr+8)*132 + mc + 9] += sO[mf][1][3] * gcol[3];
        }
    }
    __syncthreads();
    for (int x = tid; x < KD*32; x += 512) {
        int kd = x >> 5, mq = (x & 31) << 2;
        float4 v = *(const float4*)&os[kd*132 + mq];
        int c = kd / 3, d = kd - 3*c;
        *(float4*)(g_o + ((size_t)((b*C_ + h*32 + c)*3 + d))*NN + m0 + mq) = v;
    }
}

// ---------------------------------------------------------------------------
extern "C" void kernel_launch(void* const* d_in, const int* in_sizes, int n_in,
                              void* d_out, int out_size)
{
    const float* Q    = (const float*)d_in[0];
    const float* K    = (const float*)d_in[1];
    const float* Z    = (const float*)d_in[2];
    const float* Wq_w = (const float*)d_in[3];
    const float* Wq_b = (const float*)d_in[4];
    const float* Wk_w = (const float*)d_in[5];
    const float* Wk_b = (const float*)d_in[6];
    const float* Wz_w = (const float*)d_in[7];
    const float* Wz_b = (const float*)d_in[8];
    const float* Wo_w = (const float*)d_in[9];
    const float* Wo_b = (const float*)d_in[10];
    float* out = (float*)d_out;

    static int init = 0;
    if (!init) {
        cudaFuncSetAttribute(proj_tc, cudaFuncAttributeMaxDynamicSharedMemorySize, P_SMEM*4);
        cudaFuncSetAttribute(attn_tc, cudaFuncAttributeMaxDynamicSharedMemorySize, SMEM_F*4);
        init = 1;
    }

    dim3 tgrid(48, 4, B_);
    proj_tc<<<tgrid, 256, P_SMEM*4>>>(Q, Wq_w, Wq_b, 0);
    proj_tc<<<tgrid, 256, P_SMEM*4>>>(K, Wk_w, Wk_b, 1);
    proj_tc<<<tgrid, 256, P_SMEM*4>>>(Z, Wz_w, Wz_b, 2);

    dim3 agrid(NN/128, H_, B_);   // (16, 8, 4)
    attn_tc<<<agrid, 512, SMEM_F*4>>>();

    dim3 ogrid((3*NN)/64, C_/64, B_);
    proj_o<<<ogrid, 256>>>(Wo_w, Wo_b, out);
}

// round 17
// speedup vs baseline: 1.7589x; 1.0763x over previous
#include <cuda_runtime.h>
#include <cstdint>
#include <math.h>

#define B_   4
#define C_   256
#define H_   8
#define KD   96
#define NN   2048
#define EPSV 1e-6f
#define SCALE 0.10206207261596575f  // 1/sqrt(96)

static __device__ __align__(256) float g_q2[(size_t)B_*H_*NN*96];
static __device__ __align__(256) float g_k2[(size_t)B_*H_*12*NN*8];
static __device__ __align__(256) float g_z2[(size_t)B_*H_*KD*NN];
static __device__ __align__(256) float g_o [(size_t)B_*C_*3*NN];   // fp32 [b][e][d][m]

__device__ __forceinline__ float to_tf32(float x){
    float r; asm("cvt.rna.tf32.f32 %0, %1;" : "=f"(r) : "f"(x)); return r;
}
__device__ __forceinline__ unsigned fbits(float x){ return __float_as_uint(x); }

__device__ __forceinline__ void mma8(float* d, const unsigned* a, const unsigned* b){
    asm volatile("mma.sync.aligned.m16n8k8.row.col.f32.tf32.tf32.f32 "
        "{%0,%1,%2,%3},{%4,%5,%6,%7},{%8,%9},{%0,%1,%2,%3};\n"
        : "+f"(d[0]),"+f"(d[1]),"+f"(d[2]),"+f"(d[3])
        : "r"(a[0]),"r"(a[1]),"r"(a[2]),"r"(a[3]),"r"(b[0]),"r"(b[1]));
}
__device__ __forceinline__ void cp16(uint32_t dst, const float* src){
    asm volatile("cp.async.cg.shared.global [%0], [%1], 16;\n" :: "r"(dst), "l"(src));
}

// ---------------------------------------------------------------------------
// proj_tc: Y[e][col] = sum_c W[c][e] X[c][col] + bias, tf32 MMA.
// dst 0=q2(xSCALE) 1=k2 2=z2 (packed tf32); dst 3: X=g_o, natural fp32 out.
// ---------------------------------------------------------------------------
#define WST 260
#define XST 132
#define POFF_X0 (64*WST)
#define POFF_X1 (POFF_X0 + 32*XST)
#define P_SMEM  (POFF_X1 + 32*XST)

__device__ __forceinline__ void store_pkd(int dst, int b, int e, int d, int n, float v){
    int h = e >> 5, c = e & 31, kd = c*3 + d;
    size_t bh = (size_t)(b*H_ + h);
    int j = kd & 7, slot = (j&3)*2 + (j>>2);
    if (dst == 0)      g_q2[(bh*NN + n)*96 + (kd>>3)*8 + slot] = to_tf32(v * SCALE);
    else if (dst == 1) g_k2[((bh*12 + (kd>>3))*NN + n)*8 + slot] = to_tf32(v);
    else               g_z2[(bh*KD + kd)*NN + (n & ~7) + (n&3)*2 + ((n&7)>>2)] = to_tf32(v);
}

__global__ __launch_bounds__(256, 2) void proj_tc(const float* __restrict__ X0,
                                                  const float* __restrict__ W,
                                                  const float* __restrict__ Wb,
                                                  float* __restrict__ outp,
                                                  int dst)
{
    extern __shared__ float smp[];
    const int b = blockIdx.z;
    const int colBase = blockIdx.x * 128;
    const int eBase   = blockIdx.y * 64;
    const int tid = threadIdx.x, wid = tid >> 5, lane = tid & 31;
    const int qr = lane >> 2, qc = lane & 3;
    const int wm = wid & 3, wn = wid >> 2;
    const uint32_t sb = (uint32_t)__cvta_generic_to_shared(smp);
    const float* X = (dst == 3 ? g_o : X0) + (size_t)b * (C_*3*NN);

    for (int x = tid; x < 1024; x += 256) {
        int c = x >> 5, rem = x & 31;
        cp16(sb + (uint32_t)(POFF_X0 + c*XST + rem*4)*4, X + (size_t)c*(3*NN) + colBase + rem*4);
    }
    asm volatile("cp.async.commit_group;\n");

    for (int x = tid; x < 4096; x += 256) {
        int c = x >> 4, e4 = (x & 15) * 4;
        float4 w = *(const float4*)(W + (size_t)c*C_ + eBase + e4);
        int kb = c >> 3, j = c & 7;
        int slot = kb*8 + (j&3)*2 + (j>>2);
        smp[(e4+0)*WST + slot] = to_tf32(w.x);
        smp[(e4+1)*WST + slot] = to_tf32(w.y);
        smp[(e4+2)*WST + slot] = to_tf32(w.z);
        smp[(e4+3)*WST + slot] = to_tf32(w.w);
    }

    float s[8][4];
#pragma unroll
    for (int nf = 0; nf < 8; nf++){ s[nf][0]=0.f; s[nf][1]=0.f; s[nf][2]=0.f; s[nf][3]=0.f; }

    for (int st = 0; st < 8; st++) {
        asm volatile("cp.async.wait_group 0;\n");
        __syncthreads();
        const int cur = st & 1;
        if (st < 7) {
            const int c0 = (st + 1) * 32;
            const int bo = cur ? POFF_X0 : POFF_X1;
            for (int x = tid; x < 1024; x += 256) {
                int c = x >> 5, rem = x & 31;
                cp16(sb + (uint32_t)(bo + c*XST + rem*4)*4, X + (size_t)(c0 + c)*(3*NN) + colBase + rem*4);
            }
        }
        asm volatile("cp.async.commit_group;\n");
        const float* xb = smp + (cur ? POFF_X1 : POFF_X0);

#pragma unroll
        for (int kbl = 0; kbl < 4; kbl++) {
            const int kb = st*4 + kbl;
            float2 a02 = *(const float2*)(smp + (wm*16+qr)*WST + kb*8 + qc*2);
            float2 a13 = *(const float2*)(smp + (wm*16+qr+8)*WST + kb*8 + qc*2);
            unsigned a[4] = { fbits(a02.x), fbits(a13.x), fbits(a02.y), fbits(a13.y) };
            const float* bp  = xb + (kbl*8+qc)*XST + wn*64 + qr;
            const float* bp4 = bp + 4*XST;
#pragma unroll
            for (int nf = 0; nf < 8; nf++) {
                unsigned bb[2] = { fbits(to_tf32(bp[nf*8])), fbits(to_tf32(bp4[nf*8])) };
                mma8(s[nf], a, bb);
            }
        }
    }

    const int d  = colBase >> 11;
    const int e0 = eBase + wm*16 + qr, e1 = e0 + 8;
    float b00=Wb[e0*3], b01=Wb[e0*3+1], b02=Wb[e0*3+2];
    float b10=Wb[e1*3], b11=Wb[e1*3+1], b12=Wb[e1*3+2];
    const float u0 = EPSV * Wb[e0*3+d] * rsqrtf(b00*b00 + b01*b01 + b02*b02);
    const float u1 = EPSV * Wb[e1*3+d] * rsqrtf(b10*b10 + b11*b11 + b12*b12);
#pragma unroll
    for (int nf = 0; nf < 8; nf++) {
        int col = colBase + wn*64 + nf*8 + 2*qc;
        int n = col & (NN-1);
        if (dst == 3) {
            const size_t r0i = ((size_t)((b*C_ + e0)*3 + d)) * NN;
            const size_t r1i = ((size_t)((b*C_ + e1)*3 + d)) * NN;
            outp[r0i + n]     = s[nf][0] + u0;
            outp[r0i + n + 1] = s[nf][1] + u0;
            outp[r1i + n]     = s[nf][2] + u1;
            outp[r1i + n + 1] = s[nf][3] + u1;
        } else {
            store_pkd(dst, b, e0, d, n,   s[nf][0] + u0);
            store_pkd(dst, b, e0, d, n+1, s[nf][1] + u0);
            store_pkd(dst, b, e1, d, n,   s[nf][2] + u1);
            store_pkd(dst, b, e1, d, n+1, s[nf][3] + u1);
        }
    }
}

// ---------------------------------------------------------------------------
// attn_tc v2 (REVERT to the measured-best R12 config, 256 thr, + race-fix
// barrier before the os-staging epilogue).
// ---------------------------------------------------------------------------
#define QST 100
#define ZST 68
#define PST 68
#define OFF_Q  0
#define OFF_K0 12800
#define OFF_K1 18944
#define OFF_Z0 25088
#define OFF_Z1 31616
#define OFF_P  38144
#define OFF_F  46848
#define SMEM_F 46976   // floats -> 187904 B

__global__ __launch_bounds__(256) void attn_tc()
{
    extern __shared__ float sm[];
    const int bh = blockIdx.z * H_ + blockIdx.y;
    const int b = blockIdx.z, h = blockIdx.y;
    const int m0 = blockIdx.x * 128;
    const int tid = threadIdx.x, wid = tid >> 5, lane = tid & 31;
    const int qr = lane >> 2, qc = lane & 3;
    const uint32_t sb = (uint32_t)__cvta_generic_to_shared(sm);

    const float* qg = g_q2 + ((size_t)bh*NN + m0)*96;
    const float* kg = g_k2 + (size_t)bh*12*NN*8;
    const float* zg = g_z2 + (size_t)bh*KD*NN;

    for (int x = tid; x < 3072; x += 256) {
        int m = x / 24, rem = x - m*24;
        cp16(sb + (uint32_t)(OFF_Q + m*QST + rem*4)*4, qg + (size_t)m*96 + rem*4);
    }
    for (int x = tid; x < 1536; x += 256) {
        int kb = x >> 7, rem = x & 127;
        cp16(sb + (uint32_t)(OFF_K0 + kb*512 + rem*4)*4, kg + (size_t)kb*NN*8 + rem*4);
    }
    for (int x = tid; x < 1536; x += 256) {
        int kd = x >> 4, rem = x & 15;
        cp16(sb + (uint32_t)(OFF_Z0 + kd*ZST + rem*4)*4, zg + (size_t)kd*NN + rem*4);
    }
    asm volatile("cp.async.commit_group;\n");

    float sO[6][2][4];
#pragma unroll
    for (int mf = 0; mf < 6; mf++)
#pragma unroll
        for (int g = 0; g < 2; g++)
#pragma unroll
            for (int c = 0; c < 4; c++) sO[mf][g][c] = 0.f;

    float mi0 = -1e30f, mi1 = -1e30f, li0 = 0.f, li1 = 0.f;
    const int sa = ((2*qc)&3)*2 + ((2*qc)>>2);
    const int sbslot = ((2*qc+1)&3)*2 + ((2*qc+1)>>2);

    for (int t = 0; t < 32; t++) {
        asm volatile("cp.async.wait_group 0;\n");
        __syncthreads();
        const int cur = t & 1;
        if (t < 31) {
            const int n0 = (t + 1) * 64;
            const int bk = cur ? OFF_K0 : OFF_K1;
            const int bz = cur ? OFF_Z0 : OFF_Z1;
            for (int x = tid; x < 1536; x += 256) {
                int kb = x >> 7, rem = x & 127;
                cp16(sb + (uint32_t)(bk + kb*512 + rem*4)*4, kg + ((size_t)kb*NN + n0)*8 + rem*4);
            }
            for (int x = tid; x < 1536; x += 256) {
                int kd = x >> 4, rem = x & 15;
                cp16(sb + (uint32_t)(bz + kd*ZST + rem*4)*4, zg + (size_t)kd*NN + n0 + rem*4);
            }
        }
        asm volatile("cp.async.commit_group;\n");

        const float* kbuf = sm + (cur ? OFF_K1 : OFF_K0);
        const float* zbuf = sm + (cur ? OFF_Z1 : OFF_Z0);

        float s[8][4];
#pragma unroll
        for (int nf = 0; nf < 8; nf++){ s[nf][0]=0.f; s[nf][1]=0.f; s[nf][2]=0.f; s[nf][3]=0.f; }

        const float* ar0 = sm + OFF_Q + (wid*16 + qr)*QST + qc*2;
        const float* ar1 = ar0 + 8*QST;
#pragma unroll
        for (int kb = 0; kb < 12; kb++) {
            float2 a02 = *(const float2*)(ar0 + kb*8);
            float2 a13 = *(const float2*)(ar1 + kb*8);
            unsigned a[4] = { fbits(a02.x), fbits(a13.x), fbits(a02.y), fbits(a13.y) };
            const float* bp = kbuf + kb*512 + qr*8 + qc*2;
#pragma unroll
            for (int nf = 0; nf < 8; nf++) {
                float2 b2 = *(const float2*)(bp + nf*64);
                unsigned bb[2] = { fbits(b2.x), fbits(b2.y) };
                mma8(s[nf], a, bb);
            }
        }

        float rm0 = -1e30f, rm1 = -1e30f;
#pragma unroll
        for (int nf = 0; nf < 8; nf++) {
            rm0 = fmaxf(rm0, fmaxf(s[nf][0], s[nf][1]));
            rm1 = fmaxf(rm1, fmaxf(s[nf][2], s[nf][3]));
        }
        rm0 = fmaxf(rm0, __shfl_xor_sync(0xffffffffu, rm0, 1));
        rm0 = fmaxf(rm0, __shfl_xor_sync(0xffffffffu, rm0, 2));
        rm1 = fmaxf(rm1, __shfl_xor_sync(0xffffffffu, rm1, 1));
        rm1 = fmaxf(rm1, __shfl_xor_sync(0xffffffffu, rm1, 2));
        float nm0 = fmaxf(mi0, rm0), nm1 = fmaxf(mi1, rm1);
        float f0 = __expf(mi0 - nm0), f1 = __expf(mi1 - nm1);
        mi0 = nm0; mi1 = nm1;
        float sum0 = 0.f, sum1 = 0.f;
#pragma unroll
        for (int nf = 0; nf < 8; nf++) {
            s[nf][0] = __expf(s[nf][0] - nm0); s[nf][1] = __expf(s[nf][1] - nm0);
            s[nf][2] = __expf(s[nf][2] - nm1); s[nf][3] = __expf(s[nf][3] - nm1);
            sum0 += s[nf][0] + s[nf][1];
            sum1 += s[nf][2] + s[nf][3];
        }
        sum0 += __shfl_xor_sync(0xffffffffu, sum0, 1);
        sum0 += __shfl_xor_sync(0xffffffffu, sum0, 2);
        sum1 += __shfl_xor_sync(0xffffffffu, sum1, 1);
        sum1 += __shfl_xor_sync(0xffffffffu, sum1, 2);
        li0 = li0 * f0 + sum0;
        li1 = li1 * f1 + sum1;
        if (qc == 0) {
            sm[OFF_F + wid*16 + qr]     = f0;
            sm[OFF_F + wid*16 + qr + 8] = f1;
        }
        {
            float* pr0 = sm + OFF_P + (wid*16 + qr)*PST;
            float* pr1 = pr0 + 8*PST;
#pragma unroll
            for (int nf = 0; nf < 8; nf++) {
                pr0[nf*8 + sa]     = to_tf32(s[nf][0]);
                pr0[nf*8 + sbslot] = to_tf32(s[nf][1]);
                pr1[nf*8 + sa]     = to_tf32(s[nf][2]);
                pr1[nf*8 + sbslot] = to_tf32(s[nf][3]);
            }
        }
        __syncwarp();

        const float fc00 = sm[OFF_F + wid*16 + 2*qc];
        const float fc01 = sm[OFF_F + wid*16 + 2*qc + 1];
        const float fc10 = sm[OFF_F + wid*16 + 8 + 2*qc];
        const float fc11 = sm[OFF_F + wid*16 + 8 + 2*qc + 1];
#pragma unroll
        for (int mf = 0; mf < 6; mf++) {
            sO[mf][0][0] *= fc00; sO[mf][0][1] *= fc01; sO[mf][0][2] *= fc00; sO[mf][0][3] *= fc01;
            sO[mf][1][0] *= fc10; sO[mf][1][1] *= fc11; sO[mf][1][2] *= fc10; sO[mf][1][3] *= fc11;
        }

        const float* prd0 = sm + OFF_P + (wid*16 + qr)*PST + qc*2;
        const float* prd1 = prd0 + 8*PST;
#pragma unroll
        for (int nb = 0; nb < 8; nb++) {
            float2 p0 = *(const float2*)(prd0 + nb*8);
            float2 p1 = *(const float2*)(prd1 + nb*8);
            unsigned bp0[2] = { fbits(p0.x), fbits(p0.y) };
            unsigned bp1[2] = { fbits(p1.x), fbits(p1.y) };
            const float* zr = zbuf + nb*8 + qc*2;
#pragma unroll
            for (int mf = 0; mf < 6; mf++) {
                float2 z02 = *(const float2*)(zr + (mf*16 + qr)*ZST);
                float2 z13 = *(const float2*)(zr + (mf*16 + qr + 8)*ZST);
                unsigned a[4] = { fbits(z02.x), fbits(z13.x), fbits(z02.y), fbits(z13.y) };
                mma8(sO[mf][0], a, bp0);
                mma8(sO[mf][1], a, bp1);
            }
        }
    }

    // race fix: os staging overlaps OFF_K1 read by other warps' t=31 GEMM1
    __syncthreads();

    if (qc == 0) {
        sm[OFF_F + wid*16 + qr]     = li0;
        sm[OFF_F + wid*16 + qr + 8] = li1;
    }
    __syncwarp();
    const float ic00 = 1.f / sm[OFF_F + wid*16 + 2*qc];
    const float ic01 = 1.f / sm[OFF_F + wid*16 + 2*qc + 1];
    const float ic10 = 1.f / sm[OFF_F + wid*16 + 8 + 2*qc];
    const float ic11 = 1.f / sm[OFF_F + wid*16 + 8 + 2*qc + 1];

    float* os = sm + OFF_K0;
#pragma unroll
    for (int mf = 0; mf < 6; mf++) {
        const int r0 = mf*16 + qr;
        const int mc = wid*16 + 2*qc;
        os[r0*132 + mc]         = sO[mf][0][0] * ic00;
        os[r0*132 + mc + 1]     = sO[mf][0][1] * ic01;
        os[(r0+8)*132 + mc]     = sO[mf][0][2] * ic00;
        os[(r0+8)*132 + mc + 1] = sO[mf][0][3] * ic01;
        os[r0*132 + mc + 8]     = sO[mf][1][0] * ic10;
        os[r0*132 + mc + 9]     = sO[mf][1][1] * ic11;
        os[(r0+8)*132 + mc + 8] = sO[mf][1][2] * ic10;
        os[(r0+8)*132 + mc + 9] = sO[mf][1][3] * ic11;
    }
    __syncthreads();
    for (int x = tid; x < KD*32; x += 256) {
        int kd = x >> 5, mq = (x & 31) << 2;
        float4 v = *(const float4*)&os[kd*132 + mq];
        int c = kd / 3, d = kd - 3*c;
        *(float4*)(g_o + ((size_t)((b*C_ + h*32 + c)*3 + d))*NN + m0 + mq) = v;
    }
}

// ---------------------------------------------------------------------------
extern "C" void kernel_launch(void* const* d_in, const int* in_sizes, int n_in,
                              void* d_out, int out_size)
{
    const float* Q    = (const float*)d_in[0];
    const float* K    = (const float*)d_in[1];
    const float* Z    = (const float*)d_in[2];
    const float* Wq_w = (const float*)d_in[3];
    const float* Wq_b = (const float*)d_in[4];
    const float* Wk_w = (const float*)d_in[5];
    const float* Wk_b = (const float*)d_in[6];
    const float* Wz_w = (const float*)d_in[7];
    const float* Wz_b = (const float*)d_in[8];
    const float* Wo_w = (const float*)d_in[9];
    const float* Wo_b = (const float*)d_in[10];
    float* out = (float*)d_out;

    static int init = 0;
    if (!init) {
        cudaFuncSetAttribute(proj_tc, cudaFuncAttributeMaxDynamicSharedMemorySize, P_SMEM*4);
        cudaFuncSetAttribute(attn_tc, cudaFuncAttributeMaxDynamicSharedMemorySize, SMEM_F*4);
        init = 1;
    }

    dim3 tgrid(48, 4, B_);
    proj_tc<<<tgrid, 256, P_SMEM*4>>>(Q, Wq_w, Wq_b, nullptr, 0);
    proj_tc<<<tgrid, 256, P_SMEM*4>>>(K, Wk_w, Wk_b, nullptr, 1);
    proj_tc<<<tgrid, 256, P_SMEM*4>>>(Z, Wz_w, Wz_b, nullptr, 2);

    dim3 agrid(NN/128, H_, B_);   // (16, 8, 4)
    attn_tc<<<agrid, 256, SMEM_F*4>>>();

    proj_tc<<<tgrid, 256, P_SMEM*4>>>(nullptr, Wo_w, Wo_b, out, 3);
}